// round 9
// baseline (speedup 1.0000x reference)
#include <cuda_runtime.h>
#include <cuda_bf16.h>

// RocketConv: 84 ternary dilated kernels; y = -S + 3*(tap_a+tap_b+tap_c).
// Output plane index within batch: idx = c*84 + k (reshape is reinterpretation).
//
// R9 experiment: sequential per-CTA write streams. CTA = (row, group of 21
// consecutive k). Stage x row (+16 halos) and -S row in smem; iterate k
// OUTER, t-chunk inner => each CTA writes one fully sequential 336KB stream
// (vs 84 stripes at 16KB stride). Register-block ta/(ta+tb)/nS across the
// unrolled lexicographic combos so smem reads stay ~1.6 float4 per output.

#define T_LEN 4096
#define NK 84

// smem: xs[4128] (16 zero halo + 4096 + 16 zero halo), nSs[4096]
#define XS_LEN 4128
#define SMEM_FLOATS (XS_LEN + T_LEN)

extern __shared__ float smem_buf[];

template<int G>
__device__ __forceinline__ void group_body(const float* __restrict__ xs,
                                           const float* __restrict__ nSs,
                                           float* __restrict__ og, int tid)
{
    const int tbase = tid * 4;

    float4 nS[4];
#pragma unroll
    for (int ch = 0; ch < 4; ch++)
        nS[ch] = *reinterpret_cast<const float4*>(nSs + ch * 1024 + tbase);

    int kidx = 0;
#pragma unroll
    for (int a = 0; a < 9; a++) {
        float4 ta[4];
#pragma unroll
        for (int ch = 0; ch < 4; ch++)
            ta[ch] = *reinterpret_cast<const float4*>(xs + ch * 1024 + tbase + 4 * a);
#pragma unroll
        for (int b = a + 1; b < 9; b++) {
            float4 s2[4];
#pragma unroll
            for (int ch = 0; ch < 4; ch++) {
                const float4 tb = *reinterpret_cast<const float4*>(xs + ch * 1024 + tbase + 4 * b);
                s2[ch].x = ta[ch].x + tb.x;
                s2[ch].y = ta[ch].y + tb.y;
                s2[ch].z = ta[ch].z + tb.z;
                s2[ch].w = ta[ch].w + tb.w;
            }
#pragma unroll
            for (int cc = b + 1; cc < 9; cc++) {
                if (kidx / 21 == G) {   // compile-time filter after unroll
                    const int klocal = kidx - G * 21;
#pragma unroll
                    for (int ch = 0; ch < 4; ch++) {
                        const float4 tc = *reinterpret_cast<const float4*>(
                            xs + ch * 1024 + tbase + 4 * cc);
                        float4 r;
                        r.x = fmaf(3.0f, s2[ch].x + tc.x, nS[ch].x);
                        r.y = fmaf(3.0f, s2[ch].y + tc.y, nS[ch].y);
                        r.z = fmaf(3.0f, s2[ch].z + tc.z, nS[ch].z);
                        r.w = fmaf(3.0f, s2[ch].w + tc.w, nS[ch].w);
                        *reinterpret_cast<float4*>(
                            og + (size_t)klocal * T_LEN + ch * 1024 + tbase) = r;
                    }
                }
                kidx++;
            }
        }
    }
}

__global__ __launch_bounds__(256, 3) void rocketconv_kernel(
    const float* __restrict__ x, float* __restrict__ out)
{
    const int row = blockIdx.x >> 2;   // b*16 + c
    const int g   = blockIdx.x & 3;    // kgroup: k in [21g, 21g+21)
    const int tid = threadIdx.x;

    float* xs  = smem_buf;             // xs[i] = x[row][i-16], zero-padded
    float* nSs = smem_buf + XS_LEN;

    const float* __restrict__ xr = x + (size_t)row * T_LEN;

    // zero halos (32 floats, 8 threads x float4)
    if (tid < 8) {
        const int i = tid * 4;
        const float4 z = make_float4(0.f, 0.f, 0.f, 0.f);
        if (i < 16) *reinterpret_cast<float4*>(xs + i) = z;            // xs[0..15]
        else        *reinterpret_cast<float4*>(xs + 4096 + i) = z;     // xs[4112..4127]
    }
    // stage x row: 16 floats per thread
#pragma unroll
    for (int i = 0; i < 4; i++) {
        const int t = tid * 16 + i * 4;
        *reinterpret_cast<float4*>(xs + 16 + t) =
            *reinterpret_cast<const float4*>(xr + t);
    }
    __syncthreads();

    // nSs[t] = -(sum_j xs[t + 4j]) = -S(t)
#pragma unroll
    for (int i = 0; i < 4; i++) {
        const int t = tid * 16 + i * 4;
        float4 s = make_float4(0.f, 0.f, 0.f, 0.f);
#pragma unroll
        for (int j = 0; j < 9; j++) {
            const float4 v = *reinterpret_cast<const float4*>(xs + t + 4 * j);
            s.x += v.x; s.y += v.y; s.z += v.z; s.w += v.w;
        }
        *reinterpret_cast<float4*>(nSs + t) =
            make_float4(-s.x, -s.y, -s.z, -s.w);
    }
    __syncthreads();

    // out base: plane idx = c*84 + g*21 inside batch b
    const int b = row >> 4;
    const int c = row & 15;
    float* og = out + ((size_t)b * NK * 16 + (size_t)c * NK + (size_t)g * 21) * T_LEN;

    switch (g) {
        case 0: group_body<0>(xs, nSs, og, tid); break;
        case 1: group_body<1>(xs, nSs, og, tid); break;
        case 2: group_body<2>(xs, nSs, og, tid); break;
        default: group_body<3>(xs, nSs, og, tid); break;
    }
}

extern "C" void kernel_launch(void* const* d_in, const int* in_sizes, int n_in,
                              void* d_out, int out_size)
{
    const float* x = (const float*)d_in[0];
    float* out = (float*)d_out;
    // 256 rows x 4 kgroups = 1024 CTAs of 256 threads; 32.9KB smem each
    rocketconv_kernel<<<1024, 256, SMEM_FLOATS * sizeof(float)>>>(x, out);
}

// round 10
// speedup vs baseline: 2.5518x; 2.5518x over previous
#include <cuda_runtime.h>
#include <cuda_bf16.h>

// RocketConv: 84 ternary dilated kernels (alpha=-1, beta=2 at each
// lexicographic 3-combination of 9 taps), dilation 4, pad 16.
// y = -S + 3*(tap_a + tap_b + tap_c), S = sum of all 9 taps.
// Output plane index within batch: idx = c*84 + k (reshape is reinterpretation).
//
// FINAL (verified best, = R6/R8): 4 t/thread, one float4 store per kernel
// plane (warp burst = 512B fully contiguous, full sectors), default caching
// stores, 2 CTAs/SM via 76KB smem limiter. Sits at the DRAM sustained-write
// ceiling (~5.4 TB/s, 68% of spec): ncu 54.4-54.8us.
// Falsified levers (dedicated experiment each): higher occupancy (R3, worse),
// 8t/thread split stores (R4, partial-sector RMW 3.5x), finer grid (R5,
// neutral), st.global.cs (R7, -45%), sequential k-outer streams (R9, -160%).

#define T_LEN 4096
#define C_LEN 16
#define NK 84

extern __shared__ float smem_unused[];  // occupancy limiter only

__global__ __launch_bounds__(256) void rocketconv_kernel(
    const float* __restrict__ x, float* __restrict__ out)
{
    // blockIdx.x in [0, 1024): row = b*16+c (0..255), tile = quarter of T
    const int row  = blockIdx.x >> 2;
    const int tile = blockIdx.x & 3;
    const int t0   = tile * 1024 + threadIdx.x * 4;

    const float* __restrict__ xr = x + row * T_LEN;

    // v[i] = x[t0 - 16 + i], i in [0,36): tap j for lane q is v[q + 4*j]
    float v[36];
#pragma unroll
    for (int i = 0; i < 9; i++) {
        const int t = t0 - 16 + i * 4;
        if (t >= 0 && t + 3 < T_LEN) {
            const float4 f = *reinterpret_cast<const float4*>(xr + t);
            v[i * 4 + 0] = f.x; v[i * 4 + 1] = f.y;
            v[i * 4 + 2] = f.z; v[i * 4 + 3] = f.w;
        } else {
#pragma unroll
            for (int q = 0; q < 4; q++) {
                const int tt = t + q;
                v[i * 4 + q] = (tt >= 0 && tt < T_LEN) ? xr[tt] : 0.0f;
            }
        }
    }

    // -S per lane (S = sum of 9 taps)
    float nS[4];
#pragma unroll
    for (int q = 0; q < 4; q++) {
        float s = 0.0f;
#pragma unroll
        for (int j = 0; j < 9; j++) s += v[q + 4 * j];
        nS[q] = -s;
    }

    // out base: plane idx = c*84 inside batch b; row = b*16+c
    const int b = row >> 4;
    const int c = row & 15;
    float* __restrict__ o =
        out + ((size_t)b * NK * C_LEN + (size_t)c * NK) * T_LEN + t0;

    // 84 kernels in lexicographic combination order, fully unrolled so all
    // tap indices are compile-time constants (registers, no local memory).
#pragma unroll
    for (int a = 0; a < 9; a++) {
#pragma unroll
        for (int bb = a + 1; bb < 9; bb++) {
#pragma unroll
            for (int cc = bb + 1; cc < 9; cc++) {
                float4 r;
                r.x = fmaf(3.0f, v[0 + 4*a] + v[0 + 4*bb] + v[0 + 4*cc], nS[0]);
                r.y = fmaf(3.0f, v[1 + 4*a] + v[1 + 4*bb] + v[1 + 4*cc], nS[1]);
                r.z = fmaf(3.0f, v[2 + 4*a] + v[2 + 4*bb] + v[2 + 4*cc], nS[2]);
                r.w = fmaf(3.0f, v[3 + 4*a] + v[3 + 4*bb] + v[3 + 4*cc], nS[3]);
                *reinterpret_cast<float4*>(o) = r;
                o += T_LEN;  // next kernel plane (contiguous within (b,c))
            }
        }
    }
}

extern "C" void kernel_launch(void* const* d_in, const int* in_sizes, int n_in,
                              void* d_out, int out_size)
{
    const float* x = (const float*)d_in[0];
    float* out = (float*)d_out;

    cudaFuncSetAttribute(rocketconv_kernel,
                         cudaFuncAttributeMaxDynamicSharedMemorySize,
                         76 * 1024);

    // 1024 blocks of 256 threads; 76KB smem reservation -> 2 CTAs/SM.
    rocketconv_kernel<<<1024, 256, 76 * 1024>>>(x, out);
}